// round 1
// baseline (speedup 1.0000x reference)
#include <cuda_runtime.h>

// Problem shape constants
//  bs=16384, din=512, mid=1024, out=512, K=2, D1=2, D2=4
//  l1_input : (bs, 1024)  interleave(conv1_queue[0], x)
//  h1       : (bs, 1024)  = bn1(relu(l1 @ w1^T + b1))
//  l2_input : (bs, 2048)  interleave(conv2_queue[0], h1)
//  out      : (bs, 512)   = bn2(relu(l2 @ w2^T + l1 @ w_skip^T + b2 + b_skip))

#define EPSBN 1e-5f

#define BSZ   16384
#define KDIM1 1024
#define KDIM2 2048
#define NMID  1024
#define NOUT  512

// Scratch (static device arrays: allocation-free per harness rules)
__device__ float g_A1[(size_t)BSZ * KDIM1];   // 64 MB  : l1_input, dense
__device__ float g_A2[(size_t)BSZ * KDIM2];   // 128 MB : l2_input, dense

// ---------------------------------------------------------------------------
// Pack kernels: build interleaved activation matrices
// ---------------------------------------------------------------------------
__global__ void pack1_kernel(const float* __restrict__ q1,
                             const float* __restrict__ x) {
    int i = blockIdx.x * blockDim.x + threadIdx.x;   // over bs*din = 8388608
    if (i < BSZ * 512) {
        // A1[m, 2c] = q1_0[m,c]; A1[m, 2c+1] = x[m,c]
        // float2 index m*512+c == i
        float2 v = make_float2(q1[i], x[i]);
        reinterpret_cast<float2*>(g_A1)[i] = v;
    }
}

__global__ void pack2_kernel(const float* __restrict__ q2) {
    int i = blockIdx.x * blockDim.x + threadIdx.x;   // over bs*mid = 16777216
    if (i < BSZ * 1024) {
        // A2[m, 2c] = q2_0[m,c]; odd slots written by gemm1 epilogue
        g_A2[(size_t)2 * i] = q2[i];
    }
}

// ---------------------------------------------------------------------------
// Tiled SGEMM mainloop: C[128x128] += A[128xK] * B[128xK]^T   (both K-major)
// 256 threads, BK=8, per-thread 8x8 register block.
// As/Bs stored transposed: [BK][128].
// ---------------------------------------------------------------------------
__device__ __forceinline__ void mm_phase(const float* __restrict__ A,
                                         const float* __restrict__ B,
                                         int K,
                                         float* __restrict__ As,
                                         float* __restrict__ Bs,
                                         float acc[8][8]) {
    const int tid  = threadIdx.x;
    const int lrow = tid >> 1;          // 0..127
    const int lcol = (tid & 1) << 2;    // 0 or 4
    const int ty   = tid >> 4;          // 0..15
    const int tx   = tid & 15;          // 0..15

    const float* Ap = A + (size_t)lrow * K + lcol;
    const float* Bp = B + (size_t)lrow * K + lcol;

    for (int k0 = 0; k0 < K; k0 += 8) {
        float4 av = *reinterpret_cast<const float4*>(Ap + k0);
        float4 bv = *reinterpret_cast<const float4*>(Bp + k0);

        __syncthreads();   // previous tile's compute done before overwrite
        As[(lcol + 0) * 128 + lrow] = av.x;
        As[(lcol + 1) * 128 + lrow] = av.y;
        As[(lcol + 2) * 128 + lrow] = av.z;
        As[(lcol + 3) * 128 + lrow] = av.w;
        Bs[(lcol + 0) * 128 + lrow] = bv.x;
        Bs[(lcol + 1) * 128 + lrow] = bv.y;
        Bs[(lcol + 2) * 128 + lrow] = bv.z;
        Bs[(lcol + 3) * 128 + lrow] = bv.w;
        __syncthreads();

#pragma unroll
        for (int k = 0; k < 8; k++) {
            float ra[8], rb[8];
#pragma unroll
            for (int i = 0; i < 8; i++) ra[i] = As[k * 128 + ty * 8 + i];
#pragma unroll
            for (int j = 0; j < 8; j++) rb[j] = Bs[k * 128 + tx * 8 + j];
#pragma unroll
            for (int i = 0; i < 8; i++)
#pragma unroll
                for (int j = 0; j < 8; j++)
                    acc[i][j] = fmaf(ra[i], rb[j], acc[i][j]);
        }
    }
}

// ---------------------------------------------------------------------------
// GEMM1: h1 = bn1(relu(A1 @ w1^T + b1)); scatter into odd slots of A2
// grid (NMID/128, BSZ/128) = (8, 128)
// ---------------------------------------------------------------------------
__global__ __launch_bounds__(256) void gemm1_kernel(
    const float* __restrict__ w1, const float* __restrict__ b1,
    const float* __restrict__ s1, const float* __restrict__ bi1,
    const float* __restrict__ mu1, const float* __restrict__ va1) {
    __shared__ float As[8 * 128];
    __shared__ float Bs[8 * 128];

    float acc[8][8] = {};
    const int blockRow = blockIdx.y * 128;
    const int blockCol = blockIdx.x * 128;

    mm_phase(g_A1 + (size_t)blockRow * KDIM1,
             w1 + (size_t)blockCol * KDIM1, KDIM1, As, Bs, acc);

    const int ty = threadIdx.x >> 4;
    const int tx = threadIdx.x & 15;
#pragma unroll
    for (int j = 0; j < 8; j++) {
        const int n  = blockCol + tx * 8 + j;
        const float se  = s1[n] * rsqrtf(va1[n] + EPSBN);
        const float off = bi1[n] - mu1[n] * se;
        const float bb  = b1[n];
#pragma unroll
        for (int i = 0; i < 8; i++) {
            const int m = blockRow + ty * 8 + i;
            const float r = fmaxf(acc[i][j] + bb, 0.0f);
            g_A2[(size_t)m * KDIM2 + 2 * n + 1] = fmaf(r, se, off);
        }
    }
}

// ---------------------------------------------------------------------------
// GEMM2: out = bn2(relu(A2 @ w2^T + A1 @ w_skip^T + b2 + b_skip))
// grid (NOUT/128, BSZ/128) = (4, 128)
// ---------------------------------------------------------------------------
__global__ __launch_bounds__(256) void gemm2_kernel(
    const float* __restrict__ w2, const float* __restrict__ wsk,
    const float* __restrict__ b2, const float* __restrict__ bsk,
    const float* __restrict__ s2, const float* __restrict__ bi2,
    const float* __restrict__ mu2, const float* __restrict__ va2,
    float* __restrict__ out) {
    __shared__ float As[8 * 128];
    __shared__ float Bs[8 * 128];

    float acc[8][8] = {};
    const int blockRow = blockIdx.y * 128;
    const int blockCol = blockIdx.x * 128;

    mm_phase(g_A2 + (size_t)blockRow * KDIM2,
             w2 + (size_t)blockCol * KDIM2, KDIM2, As, Bs, acc);
    mm_phase(g_A1 + (size_t)blockRow * KDIM1,
             wsk + (size_t)blockCol * KDIM1, KDIM1, As, Bs, acc);

    const int ty = threadIdx.x >> 4;
    const int tx = threadIdx.x & 15;
#pragma unroll
    for (int j = 0; j < 8; j++) {
        const int n  = blockCol + tx * 8 + j;
        const float se  = s2[n] * rsqrtf(va2[n] + EPSBN);
        const float off = bi2[n] - mu2[n] * se;
        const float bb  = b2[n] + bsk[n];
#pragma unroll
        for (int i = 0; i < 8; i++) {
            const int m = blockRow + ty * 8 + i;
            const float r = fmaxf(acc[i][j] + bb, 0.0f);
            out[(size_t)m * NOUT + n] = fmaf(r, se, off);
        }
    }
}

// ---------------------------------------------------------------------------
// Launch
// ---------------------------------------------------------------------------
extern "C" void kernel_launch(void* const* d_in, const int* in_sizes, int n_in,
                              void* d_out, int out_size) {
    const float* x    = (const float*)d_in[0];
    const float* q1   = (const float*)d_in[1];   // (2, bs, 512, 1): use slice 0
    const float* q2   = (const float*)d_in[2];   // (4, bs, 1024,1): use slice 0
    const float* w1   = (const float*)d_in[3];
    const float* b1   = (const float*)d_in[4];
    const float* w2   = (const float*)d_in[5];
    const float* b2   = (const float*)d_in[6];
    const float* wsk  = (const float*)d_in[7];
    const float* bsk  = (const float*)d_in[8];
    const float* s1   = (const float*)d_in[9];
    const float* bi1  = (const float*)d_in[10];
    const float* mu1  = (const float*)d_in[11];
    const float* va1  = (const float*)d_in[12];
    const float* s2   = (const float*)d_in[13];
    const float* bi2  = (const float*)d_in[14];
    const float* mu2  = (const float*)d_in[15];
    const float* va2  = (const float*)d_in[16];
    float* out = (float*)d_out;

    (void)in_sizes; (void)n_in; (void)out_size;

    pack1_kernel<<<(BSZ * 512 + 255) / 256, 256>>>(q1, x);
    pack2_kernel<<<(BSZ * 1024 + 255) / 256, 256>>>(q2);

    dim3 g1(NMID / 128, BSZ / 128);
    gemm1_kernel<<<g1, 256>>>(w1, b1, s1, bi1, mu1, va1);

    dim3 g2(NOUT / 128, BSZ / 128);
    gemm2_kernel<<<g2, 256>>>(w2, wsk, b2, bsk, s2, bi2, mu2, va2, out);
}

// round 3
// speedup vs baseline: 1.8875x; 1.8875x over previous
#include <cuda_runtime.h>
#include <cuda_bf16.h>
#include <stdint.h>

// Shapes: bs=16384, din=512, mid=1024, out=512, K=2, D1=2, D2=4
//
// Two bf16 split-precision GEMMs via mma.sync (plain PTX, works under compute_103):
//   A1 (bs x 1024)  = interleave(q1_0, x)
//   h1 (bs x 1024)  = bn1(relu(A1 @ w1^T + b1))
//   A2 (bs x 3072)  = [q2_0 (1024) | h1 (1024) | A1 (1024)]   (K-reordered)
//   WC (512 x 3072) = [w2 even cols | w2 odd cols | w_skip]
//   out (bs x 512)  = bn2(relu(A2 @ WC^T + b2 + b_skip))
// Split precision: X = Xh + Xl (bf16); 3 MMA phases: Ah*Bh + Al*Bh + Ah*Bl.

#define BSZ   16384
#define KD1   1024
#define KD2   3072
#define NMID  1024
#define NOUT  512
#define EPSBN 1e-5f

#define BM 128
#define BN 128
#define BK 64                      // bf16 elems -> 128B rows (SW128-friendly)
#define STAGES 4
#define TILE_BYTES  (128 * 128)    // 16 KB (128 rows x 128 B)
#define STAGE_BYTES (2 * TILE_BYTES)
#define SMEM_BYTES  (STAGES * STAGE_BYTES)   // 128 KB

// ---------------------------------------------------------------------------
// Scratch (static device arrays: allocation-free)
// ---------------------------------------------------------------------------
static __device__ __nv_bfloat16 g_A1h[(size_t)BSZ*KD1];
static __device__ __nv_bfloat16 g_A1l[(size_t)BSZ*KD1];
static __device__ __nv_bfloat16 g_A2h[(size_t)BSZ*KD2];
static __device__ __nv_bfloat16 g_A2l[(size_t)BSZ*KD2];
static __device__ __nv_bfloat16 g_W1h[(size_t)NMID*KD1];
static __device__ __nv_bfloat16 g_W1l[(size_t)NMID*KD1];
static __device__ __nv_bfloat16 g_WCh[(size_t)NOUT*KD2];
static __device__ __nv_bfloat16 g_WCl[(size_t)NOUT*KD2];

// ---------------------------------------------------------------------------
// PTX helpers (all plain sm_80-era PTX — no 'a' features)
// ---------------------------------------------------------------------------
__device__ __forceinline__ uint32_t smem_u32(const void* p) {
    uint32_t a;
    asm("{ .reg .u64 t; cvta.to.shared.u64 t, %1; cvt.u32.u64 %0, t; }" : "=r"(a) : "l"(p));
    return a;
}
__device__ __forceinline__ void cp16(uint32_t s, const void* g) {
    asm volatile("cp.async.cg.shared.global [%0], [%1], 16;" :: "r"(s), "l"(g));
}
__device__ __forceinline__ void cp_commit() {
    asm volatile("cp.async.commit_group;" ::: "memory");
}
__device__ __forceinline__ void cp_wait2() {
    asm volatile("cp.async.wait_group 2;" ::: "memory");
}
__device__ __forceinline__ void ldm4(uint32_t& r0, uint32_t& r1, uint32_t& r2, uint32_t& r3,
                                     uint32_t addr) {
    asm volatile("ldmatrix.sync.aligned.m8n8.x4.shared.b16 {%0,%1,%2,%3}, [%4];"
                 : "=r"(r0), "=r"(r1), "=r"(r2), "=r"(r3) : "r"(addr));
}
__device__ __forceinline__ void mma16816(float* c, const uint32_t* a, const uint32_t* b) {
    asm volatile("mma.sync.aligned.m16n8k16.row.col.f32.bf16.bf16.f32 "
                 "{%0,%1,%2,%3}, {%4,%5,%6,%7}, {%8,%9}, {%0,%1,%2,%3};"
                 : "+f"(c[0]), "+f"(c[1]), "+f"(c[2]), "+f"(c[3])
                 : "r"(a[0]), "r"(a[1]), "r"(a[2]), "r"(a[3]), "r"(b[0]), "r"(b[1]));
}
__device__ __forceinline__ uint32_t sw128(uint32_t o) { return o ^ ((o >> 3) & 0x70); }

__device__ __forceinline__ void bsplit(float v, __nv_bfloat16& h, __nv_bfloat16& l) {
    h = __float2bfloat16(v);
    l = __float2bfloat16(v - __bfloat162float(h));
}

// ---------------------------------------------------------------------------
// Pack kernels (fp32 -> bf16 hi/lo)
// ---------------------------------------------------------------------------
__global__ void pack_a1(const float* __restrict__ q1, const float* __restrict__ x) {
    int i = blockIdx.x * blockDim.x + threadIdx.x;
    if (i >= BSZ * 512) return;
    int m = i >> 9, c = i & 511;
    __nv_bfloat16 h0, l0, h1, l1;
    bsplit(q1[i], h0, l0);
    bsplit(x[i],  h1, l1);
    __nv_bfloat162 hp = __halves2bfloat162(h0, h1);
    __nv_bfloat162 lp = __halves2bfloat162(l0, l1);
    size_t o1 = (size_t)m * KD1 + 2 * c;
    *reinterpret_cast<__nv_bfloat162*>(&g_A1h[o1]) = hp;
    *reinterpret_cast<__nv_bfloat162*>(&g_A1l[o1]) = lp;
    size_t o2 = (size_t)m * KD2 + 2048 + 2 * c;          // A1 copy region of A2
    *reinterpret_cast<__nv_bfloat162*>(&g_A2h[o2]) = hp;
    *reinterpret_cast<__nv_bfloat162*>(&g_A2l[o2]) = lp;
}

__global__ void pack_a2q(const float* __restrict__ q2) {
    int i = blockIdx.x * blockDim.x + threadIdx.x;
    if (i >= BSZ * 1024) return;
    int m = i >> 10, c = i & 1023;
    __nv_bfloat16 h, l;
    bsplit(q2[i], h, l);
    size_t o = (size_t)m * KD2 + c;                      // q2 region: cols 0..1023
    g_A2h[o] = h;
    g_A2l[o] = l;
}

__global__ void pack_w1(const float* __restrict__ w1) {
    int i = blockIdx.x * blockDim.x + threadIdx.x;
    if (i >= NMID * KD1) return;
    __nv_bfloat16 h, l;
    bsplit(w1[i], h, l);
    g_W1h[i] = h; g_W1l[i] = l;
}

__global__ void pack_wcat(const float* __restrict__ w2, const float* __restrict__ wsk) {
    int i = blockIdx.x * blockDim.x + threadIdx.x;
    if (i >= NOUT * KD2) return;
    int n = i / KD2, j = i - n * KD2;
    float v;
    if (j < 1024)       v = w2[(size_t)n * 2048 + 2 * j];               // pairs q2
    else if (j < 2048)  v = w2[(size_t)n * 2048 + 2 * (j - 1024) + 1];  // pairs h1
    else                v = wsk[(size_t)n * 1024 + (j - 2048)];         // skip
    __nv_bfloat16 h, l;
    bsplit(v, h, l);
    g_WCh[i] = h; g_WCl[i] = l;
}

// ---------------------------------------------------------------------------
// mma.sync GEMM: 128x128 CTA tile, BK=64, 4-stage cp.async pipeline.
// 8 warps: warp_m = wid&1 (64 rows), warp_n = wid>>1 (32 cols).
// MODE 0: A1 @ W1^T  -> h1 (bf16 hi/lo) into A2 cols 1024..2047
// MODE 1: A2 @ WC^T  -> fp32 out
// ---------------------------------------------------------------------------
template<int MODE>
__global__ void __launch_bounds__(256) gemm_kernel(
    const float* __restrict__ pb0, const float* __restrict__ pb1,
    const float* __restrict__ psc, const float* __restrict__ pbi,
    const float* __restrict__ pmu, const float* __restrict__ pva,
    float* __restrict__ outp)
{
    extern __shared__ __align__(1024) char smem[];
    const uint32_t sb = smem_u32(smem);
    const int tid = threadIdx.x;
    const int wid = tid >> 5, lane = tid & 31;
    const int warp_m = wid & 1;      // 0..1
    const int warp_n = wid >> 1;     // 0..3
    const int blockRow = blockIdx.y * BM, blockCol = blockIdx.x * BN;

    constexpr int KDIM = (MODE == 0) ? KD1 : KD2;
    constexpr int KC   = KDIM / BK;          // chunks per phase
    constexpr int TOT  = 3 * KC;             // total chunks

    const __nv_bfloat16* Ah = (MODE == 0) ? g_A1h : g_A2h;
    const __nv_bfloat16* Al = (MODE == 0) ? g_A1l : g_A2l;
    const __nv_bfloat16* Bh = (MODE == 0) ? g_W1h : g_WCh;
    const __nv_bfloat16* Bl = (MODE == 0) ? g_W1l : g_WCl;

    // cp.async layout: thread t loads row t/2 of A and of B, half a 128B row each.
    const int ldrow = tid >> 1;
    const int ldc0  = (tid & 1) * 4;        // 16B-chunk start (0 or 4)
    const __nv_bfloat16* ArH = Ah + (size_t)(blockRow + ldrow) * KDIM;
    const __nv_bfloat16* ArL = Al + (size_t)(blockRow + ldrow) * KDIM;
    const __nv_bfloat16* BrH = Bh + (size_t)(blockCol + ldrow) * KDIM;
    const __nv_bfloat16* BrL = Bl + (size_t)(blockCol + ldrow) * KDIM;
    uint32_t swoff[4];
    #pragma unroll
    for (int i = 0; i < 4; i++)
        swoff[i] = sw128((uint32_t)ldrow * 128u + (uint32_t)(ldc0 + i) * 16u);

    auto load_chunk = [&](int j) {
        int p  = (j >= 2 * KC) ? 2 : ((j >= KC) ? 1 : 0);
        int kc = j - p * KC;
        const __nv_bfloat16* Ar = (p == 1) ? ArL : ArH;
        const __nv_bfloat16* Br = (p == 2) ? BrL : BrH;
        const char* ga = (const char*)(Ar + kc * BK) + ldc0 * 16;
        const char* gb = (const char*)(Br + kc * BK) + ldc0 * 16;
        uint32_t bs_ = sb + (uint32_t)(j % STAGES) * STAGE_BYTES;
        #pragma unroll
        for (int i = 0; i < 4; i++) cp16(bs_ + swoff[i], ga + i * 16);
        #pragma unroll
        for (int i = 0; i < 4; i++) cp16(bs_ + TILE_BYTES + swoff[i], gb + i * 16);
    };

    float acc[4][4][4] = {};    // [mtile][ntile][frag]

    // ldmatrix per-thread row/halves
    const int lrow16 = lane & 15;          // row within 16-row tile
    const int lhalf  = lane >> 4;          // 0/1 -> k-halves

    // prologue
    #pragma unroll
    for (int j = 0; j < 3; j++) { load_chunk(j); cp_commit(); }

    for (int i = 0; i < TOT; i++) {
        cp_wait2();
        __syncthreads();
        int jn = i + 3;
        if (jn < TOT) load_chunk(jn);
        cp_commit();

        uint32_t sA = sb + (uint32_t)(i % STAGES) * STAGE_BYTES;
        uint32_t sB = sA + TILE_BYTES;

        #pragma unroll
        for (int k16 = 0; k16 < 4; k16++) {
            const uint32_t chunk = (uint32_t)(k16 * 2 + lhalf) * 16u;
            uint32_t a[4][4], b[4][2];
            #pragma unroll
            for (int it = 0; it < 4; it++) {
                uint32_t row = (uint32_t)(warp_m * 64 + it * 16 + lrow16);
                ldm4(a[it][0], a[it][1], a[it][2], a[it][3],
                     sA + sw128(row * 128u + chunk));
            }
            #pragma unroll
            for (int j2 = 0; j2 < 2; j2++) {
                uint32_t row = (uint32_t)(warp_n * 32 + j2 * 16 + lrow16);
                uint32_t r0, r1, r2, r3;
                ldm4(r0, r1, r2, r3, sB + sw128(row * 128u + chunk));
                b[2*j2  ][0] = r0; b[2*j2  ][1] = r2;
                b[2*j2+1][0] = r1; b[2*j2+1][1] = r3;
            }
            #pragma unroll
            for (int it = 0; it < 4; it++)
                #pragma unroll
                for (int jt = 0; jt < 4; jt++)
                    mma16816(acc[it][jt], a[it], b[jt]);
        }
    }

    // ------------------- epilogue -------------------
    __syncthreads();     // all HMMA consumed smem; safe to reuse
    float* sp = (float*)smem;
    if (tid < BN) {
        int n = blockCol + tid;
        float se = psc[n] * rsqrtf(pva[n] + EPSBN);
        sp[tid]           = se;
        sp[BN + tid]      = pbi[n] - pmu[n] * se;
        sp[2 * BN + tid]  = (MODE == 0) ? pb0[n] : (pb0[n] + pb1[n]);
    }
    __syncthreads();

    const int groupID = lane >> 2;
    const int colPair = (lane & 3) * 2;

    #pragma unroll
    for (int it = 0; it < 4; it++) {
        #pragma unroll
        for (int jt = 0; jt < 4; jt++) {
            int lc = warp_n * 32 + jt * 8 + colPair;      // col within block
            float se0 = sp[lc],     se1 = sp[lc + 1];
            float of0 = sp[BN+lc],  of1 = sp[BN+lc+1];
            float bb0 = sp[2*BN+lc], bb1 = sp[2*BN+lc+1];
            #pragma unroll
            for (int rr = 0; rr < 2; rr++) {
                int m = blockRow + warp_m * 64 + it * 16 + groupID + rr * 8;
                float v0 = fmaf(fmaxf(acc[it][jt][2*rr]   + bb0, 0.0f), se0, of0);
                float v1 = fmaf(fmaxf(acc[it][jt][2*rr+1] + bb1, 0.0f), se1, of1);
                if (MODE == 0) {
                    __nv_bfloat16 h0, l0, h1, l1;
                    bsplit(v0, h0, l0);
                    bsplit(v1, h1, l1);
                    size_t o = (size_t)m * KD2 + 1024 + blockCol + lc;
                    *reinterpret_cast<__nv_bfloat162*>(&g_A2h[o]) = __halves2bfloat162(h0, h1);
                    *reinterpret_cast<__nv_bfloat162*>(&g_A2l[o]) = __halves2bfloat162(l0, l1);
                } else {
                    size_t o = (size_t)m * NOUT + blockCol + lc;
                    *reinterpret_cast<float2*>(&outp[o]) = make_float2(v0, v1);
                }
            }
        }
    }
}

// ---------------------------------------------------------------------------
// Launch
// ---------------------------------------------------------------------------
extern "C" void kernel_launch(void* const* d_in, const int* in_sizes, int n_in,
                              void* d_out, int out_size) {
    const float* x    = (const float*)d_in[0];
    const float* q1   = (const float*)d_in[1];   // (2, bs, 512, 1): slice 0
    const float* q2   = (const float*)d_in[2];   // (4, bs, 1024,1): slice 0
    const float* w1   = (const float*)d_in[3];
    const float* b1   = (const float*)d_in[4];
    const float* w2   = (const float*)d_in[5];
    const float* b2   = (const float*)d_in[6];
    const float* wsk  = (const float*)d_in[7];
    const float* bsk  = (const float*)d_in[8];
    const float* s1   = (const float*)d_in[9];
    const float* bi1  = (const float*)d_in[10];
    const float* mu1  = (const float*)d_in[11];
    const float* va1  = (const float*)d_in[12];
    const float* s2   = (const float*)d_in[13];
    const float* bi2  = (const float*)d_in[14];
    const float* mu2  = (const float*)d_in[15];
    const float* va2  = (const float*)d_in[16];
    float* out = (float*)d_out;
    (void)in_sizes; (void)n_in; (void)out_size;

    static bool attr_done = false;
    if (!attr_done) {
        cudaFuncSetAttribute(gemm_kernel<0>, cudaFuncAttributeMaxDynamicSharedMemorySize, SMEM_BYTES);
        cudaFuncSetAttribute(gemm_kernel<1>, cudaFuncAttributeMaxDynamicSharedMemorySize, SMEM_BYTES);
        attr_done = true;
    }

    pack_a1 <<<(BSZ * 512  + 255) / 256, 256>>>(q1, x);
    pack_a2q<<<(BSZ * 1024 + 255) / 256, 256>>>(q2);
    pack_w1 <<<(NMID * KD1 + 255) / 256, 256>>>(w1);
    pack_wcat<<<(NOUT * KD2 + 255) / 256, 256>>>(w2, wsk);

    dim3 g1(NMID / BN, BSZ / BM);   // (8, 128)
    gemm_kernel<0><<<g1, 256, SMEM_BYTES>>>(b1, nullptr, s1, bi1, mu1, va1, nullptr);

    dim3 g2(NOUT / BN, BSZ / BM);   // (4, 128)
    gemm_kernel<1><<<g2, 256, SMEM_BYTES>>>(b2, bsk, s2, bi2, mu2, va2, out);
}

// round 5
// speedup vs baseline: 2.1990x; 1.1650x over previous
#include <cuda_runtime.h>
#include <cuda_bf16.h>
#include <stdint.h>

// Shapes: bs=16384, din=512, mid=1024, out=512, K=2, D1=2, D2=4
//
// Two bf16 split-precision GEMMs via mma.sync (plain PTX under compute_103):
//   A1 (bs x 1024)  = interleave(q1_0, x)
//   h1 (bs x 1024)  = bn1(relu(A1 @ w1^T + b1))
//   A2 (bs x 3072)  = [q2_0 (1024) | h1 (1024) | A1 (1024)]   (K-reordered)
//   WC (512 x 3072) = [w2 even cols | w2 odd cols | w_skip]
//   out (bs x 512)  = bn2(relu(A2 @ WC^T + b2 + b_skip))
// Split precision, FUSED single pass: per K-chunk load (Ah,Al,Bh,Bl), compute
// Ah*Bh + Al*Bh + Ah*Bl into one fp32 accumulator (drop Al*Bl ~ 2^-16).

#define BSZ   16384
#define KD1   1024
#define KD2   3072
#define NMID  1024
#define NOUT  512
#define EPSBN 1e-5f

#define BM 128
#define BN 128
#define BK 64                        // bf16 elems -> 128B rows
#define STAGES 3
#define TILE_BYTES  (128 * 128)      // 16 KB per tile (128 rows x 128 B)
#define STAGE_BYTES (4 * TILE_BYTES) // Ah | Al | Bh | Bl
#define SMEM_BYTES  (STAGES * STAGE_BYTES)   // 192 KB

// ---------------------------------------------------------------------------
// Scratch (static device arrays: allocation-free)
// ---------------------------------------------------------------------------
static __device__ __nv_bfloat16 g_A1h[(size_t)BSZ*KD1];
static __device__ __nv_bfloat16 g_A1l[(size_t)BSZ*KD1];
static __device__ __nv_bfloat16 g_A2h[(size_t)BSZ*KD2];
static __device__ __nv_bfloat16 g_A2l[(size_t)BSZ*KD2];
static __device__ __nv_bfloat16 g_W1h[(size_t)NMID*KD1];
static __device__ __nv_bfloat16 g_W1l[(size_t)NMID*KD1];
static __device__ __nv_bfloat16 g_WCh[(size_t)NOUT*KD2];
static __device__ __nv_bfloat16 g_WCl[(size_t)NOUT*KD2];

// ---------------------------------------------------------------------------
// PTX helpers (plain sm_80-era PTX)
// ---------------------------------------------------------------------------
__device__ __forceinline__ uint32_t smem_u32(const void* p) {
    uint32_t a;
    asm("{ .reg .u64 t; cvta.to.shared.u64 t, %1; cvt.u32.u64 %0, t; }" : "=r"(a) : "l"(p));
    return a;
}
__device__ __forceinline__ void cp16(uint32_t s, const void* g) {
    asm volatile("cp.async.cg.shared.global [%0], [%1], 16;" :: "r"(s), "l"(g));
}
__device__ __forceinline__ void cp_commit() {
    asm volatile("cp.async.commit_group;" ::: "memory");
}
__device__ __forceinline__ void cp_wait1() {
    asm volatile("cp.async.wait_group 1;" ::: "memory");
}
__device__ __forceinline__ void ldm4(uint32_t& r0, uint32_t& r1, uint32_t& r2, uint32_t& r3,
                                     uint32_t addr) {
    asm volatile("ldmatrix.sync.aligned.m8n8.x4.shared.b16 {%0,%1,%2,%3}, [%4];"
                 : "=r"(r0), "=r"(r1), "=r"(r2), "=r"(r3) : "r"(addr));
}
__device__ __forceinline__ void mma16816(float* c, const uint32_t* a, const uint32_t* b) {
    asm volatile("mma.sync.aligned.m16n8k16.row.col.f32.bf16.bf16.f32 "
                 "{%0,%1,%2,%3}, {%4,%5,%6,%7}, {%8,%9}, {%0,%1,%2,%3};"
                 : "+f"(c[0]), "+f"(c[1]), "+f"(c[2]), "+f"(c[3])
                 : "r"(a[0]), "r"(a[1]), "r"(a[2]), "r"(a[3]), "r"(b[0]), "r"(b[1]));
}
__device__ __forceinline__ uint32_t sw128(uint32_t o) { return o ^ ((o >> 3) & 0x70); }

__device__ __forceinline__ void bsplit(float v, __nv_bfloat16& h, __nv_bfloat16& l) {
    h = __float2bfloat16(v);
    l = __float2bfloat16(v - __bfloat162float(h));
}

// ---------------------------------------------------------------------------
// Pack kernels (fp32 -> bf16 hi/lo)
// ---------------------------------------------------------------------------
__global__ void pack_a1(const float* __restrict__ q1, const float* __restrict__ x) {
    int i = blockIdx.x * blockDim.x + threadIdx.x;
    if (i >= BSZ * 512) return;
    int m = i >> 9, c = i & 511;
    __nv_bfloat16 h0, l0, h1, l1;
    bsplit(q1[i], h0, l0);
    bsplit(x[i],  h1, l1);
    __nv_bfloat162 hp = __halves2bfloat162(h0, h1);
    __nv_bfloat162 lp = __halves2bfloat162(l0, l1);
    size_t o1 = (size_t)m * KD1 + 2 * c;
    *reinterpret_cast<__nv_bfloat162*>(&g_A1h[o1]) = hp;
    *reinterpret_cast<__nv_bfloat162*>(&g_A1l[o1]) = lp;
    size_t o2 = (size_t)m * KD2 + 2048 + 2 * c;          // A1 copy region of A2
    *reinterpret_cast<__nv_bfloat162*>(&g_A2h[o2]) = hp;
    *reinterpret_cast<__nv_bfloat162*>(&g_A2l[o2]) = lp;
}

__global__ void pack_a2q(const float* __restrict__ q2) {
    int i = blockIdx.x * blockDim.x + threadIdx.x;        // over BSZ*512 pairs
    if (i >= BSZ * 512) return;
    int m = i >> 9, c2 = (i & 511) * 2;
    float2 v = reinterpret_cast<const float2*>(q2)[i];
    __nv_bfloat16 h0, l0, h1, l1;
    bsplit(v.x, h0, l0);
    bsplit(v.y, h1, l1);
    size_t o = (size_t)m * KD2 + c2;
    *reinterpret_cast<__nv_bfloat162*>(&g_A2h[o]) = __halves2bfloat162(h0, h1);
    *reinterpret_cast<__nv_bfloat162*>(&g_A2l[o]) = __halves2bfloat162(l0, l1);
}

__global__ void pack_w1(const float* __restrict__ w1) {
    int i = blockIdx.x * blockDim.x + threadIdx.x;        // pairs
    if (i >= NMID * KD1 / 2) return;
    float2 v = reinterpret_cast<const float2*>(w1)[i];
    __nv_bfloat16 h0, l0, h1, l1;
    bsplit(v.x, h0, l0);
    bsplit(v.y, h1, l1);
    *reinterpret_cast<__nv_bfloat162*>(&g_W1h[2*i]) = __halves2bfloat162(h0, h1);
    *reinterpret_cast<__nv_bfloat162*>(&g_W1l[2*i]) = __halves2bfloat162(l0, l1);
}

__global__ void pack_wcat(const float* __restrict__ w2, const float* __restrict__ wsk) {
    int i = blockIdx.x * blockDim.x + threadIdx.x;
    if (i >= NOUT * KD2) return;
    int n = i / KD2, j = i - n * KD2;
    float v;
    if (j < 1024)       v = w2[(size_t)n * 2048 + 2 * j];               // pairs q2
    else if (j < 2048)  v = w2[(size_t)n * 2048 + 2 * (j - 1024) + 1];  // pairs h1
    else                v = wsk[(size_t)n * 1024 + (j - 2048)];         // skip
    __nv_bfloat16 h, l;
    bsplit(v, h, l);
    g_WCh[i] = h; g_WCl[i] = l;
}

// ---------------------------------------------------------------------------
// Fused 3-term mma.sync GEMM: 128x128 CTA, BK=64, 3-stage cp.async pipeline.
// 8 warps: warp_m = wid&1 (64 rows), warp_n = wid>>1 (32 cols).
// MODE 0: A1 @ W1^T  -> h1 (bf16 hi/lo) into A2 cols 1024..2047
// MODE 1: A2 @ WC^T  -> fp32 out
// ---------------------------------------------------------------------------
template<int MODE>
__global__ void __launch_bounds__(256) gemm_kernel(
    const float* __restrict__ pb0, const float* __restrict__ pb1,
    const float* __restrict__ psc, const float* __restrict__ pbi,
    const float* __restrict__ pmu, const float* __restrict__ pva,
    float* __restrict__ outp)
{
    extern __shared__ __align__(1024) char smem[];
    const uint32_t sb = smem_u32(smem);
    const int tid = threadIdx.x;
    const int wid = tid >> 5, lane = tid & 31;
    const int warp_m = wid & 1;      // 0..1
    const int warp_n = wid >> 1;     // 0..3
    const int blockRow = blockIdx.y * BM, blockCol = blockIdx.x * BN;

    constexpr int KDIM = (MODE == 0) ? KD1 : KD2;
    constexpr int KC   = KDIM / BK;          // pipeline chunks

    const __nv_bfloat16* Ah = (MODE == 0) ? g_A1h : g_A2h;
    const __nv_bfloat16* Al = (MODE == 0) ? g_A1l : g_A2l;
    const __nv_bfloat16* Bh = (MODE == 0) ? g_W1h : g_WCh;
    const __nv_bfloat16* Bl = (MODE == 0) ? g_W1l : g_WCl;

    // cp.async: thread t covers row t/2 (half-row each) of all 4 tiles.
    const int ldrow = tid >> 1;
    const int ldc0  = (tid & 1) * 4;
    const __nv_bfloat16* ArH = Ah + (size_t)(blockRow + ldrow) * KDIM;
    const __nv_bfloat16* ArL = Al + (size_t)(blockRow + ldrow) * KDIM;
    const __nv_bfloat16* BrH = Bh + (size_t)(blockCol + ldrow) * KDIM;
    const __nv_bfloat16* BrL = Bl + (size_t)(blockCol + ldrow) * KDIM;
    uint32_t swoff[4];
    #pragma unroll
    for (int i = 0; i < 4; i++)
        swoff[i] = sw128((uint32_t)ldrow * 128u + (uint32_t)(ldc0 + i) * 16u);

    auto load_chunk = [&](int j) {
        const char* gah = (const char*)(ArH + j * BK) + ldc0 * 16;
        const char* gal = (const char*)(ArL + j * BK) + ldc0 * 16;
        const char* gbh = (const char*)(BrH + j * BK) + ldc0 * 16;
        const char* gbl = (const char*)(BrL + j * BK) + ldc0 * 16;
        uint32_t bs_ = sb + (uint32_t)(j % STAGES) * STAGE_BYTES;
        #pragma unroll
        for (int i = 0; i < 4; i++) cp16(bs_ +                swoff[i], gah + i * 16);
        #pragma unroll
        for (int i = 0; i < 4; i++) cp16(bs_ + 1*TILE_BYTES + swoff[i], gal + i * 16);
        #pragma unroll
        for (int i = 0; i < 4; i++) cp16(bs_ + 2*TILE_BYTES + swoff[i], gbh + i * 16);
        #pragma unroll
        for (int i = 0; i < 4; i++) cp16(bs_ + 3*TILE_BYTES + swoff[i], gbl + i * 16);
    };

    float acc[4][4][4] = {};    // [mtile][ntile][frag]

    const int lrow16 = lane & 15;
    const int lhalf  = lane >> 4;

    // prologue: 2 chunks in flight
    load_chunk(0); cp_commit();
    load_chunk(1); cp_commit();

    for (int i = 0; i < KC; i++) {
        cp_wait1();            // chunk i resident
        __syncthreads();
        if (i + 2 < KC) load_chunk(i + 2);
        cp_commit();

        uint32_t sAh = sb + (uint32_t)(i % STAGES) * STAGE_BYTES;
        uint32_t sAl = sAh + 1 * TILE_BYTES;
        uint32_t sBh = sAh + 2 * TILE_BYTES;
        uint32_t sBl = sAh + 3 * TILE_BYTES;

        #pragma unroll
        for (int k16 = 0; k16 < 4; k16++) {
            const uint32_t chunk = (uint32_t)(k16 * 2 + lhalf) * 16u;
            uint32_t ah[4][4], al[4][4], bh[4][2], bl[4][2];
            #pragma unroll
            for (int it = 0; it < 4; it++) {
                uint32_t ro = sw128((uint32_t)(warp_m * 64 + it * 16 + lrow16) * 128u + chunk);
                ldm4(ah[it][0], ah[it][1], ah[it][2], ah[it][3], sAh + ro);
                ldm4(al[it][0], al[it][1], al[it][2], al[it][3], sAl + ro);
            }
            #pragma unroll
            for (int j2 = 0; j2 < 2; j2++) {
                uint32_t ro = sw128((uint32_t)(warp_n * 32 + j2 * 16 + lrow16) * 128u + chunk);
                uint32_t r0, r1, r2, r3;
                ldm4(r0, r1, r2, r3, sBh + ro);
                bh[2*j2  ][0] = r0; bh[2*j2  ][1] = r2;
                bh[2*j2+1][0] = r1; bh[2*j2+1][1] = r3;
                ldm4(r0, r1, r2, r3, sBl + ro);
                bl[2*j2  ][0] = r0; bl[2*j2  ][1] = r2;
                bl[2*j2+1][0] = r1; bl[2*j2+1][1] = r3;
            }
            #pragma unroll
            for (int it = 0; it < 4; it++)
                #pragma unroll
                for (int jt = 0; jt < 4; jt++) {
                    mma16816(acc[it][jt], ah[it], bh[jt]);   // Ah*Bh
                    mma16816(acc[it][jt], al[it], bh[jt]);   // Al*Bh
                    mma16816(acc[it][jt], ah[it], bl[jt]);   // Ah*Bl
                }
        }
    }

    // ------------------- epilogue -------------------
    __syncthreads();
    float* sp = (float*)smem;
    if (tid < BN) {
        int n = blockCol + tid;
        float se = psc[n] * rsqrtf(pva[n] + EPSBN);
        sp[tid]           = se;
        sp[BN + tid]      = pbi[n] - pmu[n] * se;
        sp[2 * BN + tid]  = (MODE == 0) ? pb0[n] : (pb0[n] + pb1[n]);
    }
    __syncthreads();

    const int groupID = lane >> 2;
    const int colPair = (lane & 3) * 2;

    #pragma unroll
    for (int it = 0; it < 4; it++) {
        #pragma unroll
        for (int jt = 0; jt < 4; jt++) {
            int lc = warp_n * 32 + jt * 8 + colPair;
            float se0 = sp[lc],      se1 = sp[lc + 1];
            float of0 = sp[BN+lc],   of1 = sp[BN+lc+1];
            float bb0 = sp[2*BN+lc], bb1 = sp[2*BN+lc+1];
            #pragma unroll
            for (int rr = 0; rr < 2; rr++) {
                int m = blockRow + warp_m * 64 + it * 16 + groupID + rr * 8;
                float v0 = fmaf(fmaxf(acc[it][jt][2*rr]   + bb0, 0.0f), se0, of0);
                float v1 = fmaf(fmaxf(acc[it][jt][2*rr+1] + bb1, 0.0f), se1, of1);
                if (MODE == 0) {
                    __nv_bfloat16 h0, l0, h1, l1;
                    bsplit(v0, h0, l0);
                    bsplit(v1, h1, l1);
                    size_t o = (size_t)m * KD2 + 1024 + blockCol + lc;
                    *reinterpret_cast<__nv_bfloat162*>(&g_A2h[o]) = __halves2bfloat162(h0, h1);
                    *reinterpret_cast<__nv_bfloat162*>(&g_A2l[o]) = __halves2bfloat162(l0, l1);
                } else {
                    size_t o = (size_t)m * NOUT + blockCol + lc;
                    *reinterpret_cast<float2*>(&outp[o]) = make_float2(v0, v1);
                }
            }
        }
    }
}

// ---------------------------------------------------------------------------
// Launch (no static guards — identical work on every call, per harness rules)
// ---------------------------------------------------------------------------
extern "C" void kernel_launch(void* const* d_in, const int* in_sizes, int n_in,
                              void* d_out, int out_size) {
    const float* x    = (const float*)d_in[0];
    const float* q1   = (const float*)d_in[1];   // (2, bs, 512, 1): slice 0
    const float* q2   = (const float*)d_in[2];   // (4, bs, 1024,1): slice 0
    const float* w1   = (const float*)d_in[3];
    const float* b1   = (const float*)d_in[4];
    const float* w2   = (const float*)d_in[5];
    const float* b2   = (const float*)d_in[6];
    const float* wsk  = (const float*)d_in[7];
    const float* bsk  = (const float*)d_in[8];
    const float* s1   = (const float*)d_in[9];
    const float* bi1  = (const float*)d_in[10];
    const float* mu1  = (const float*)d_in[11];
    const float* va1  = (const float*)d_in[12];
    const float* s2   = (const float*)d_in[13];
    const float* bi2  = (const float*)d_in[14];
    const float* mu2  = (const float*)d_in[15];
    const float* va2  = (const float*)d_in[16];
    float* out = (float*)d_out;
    (void)in_sizes; (void)n_in; (void)out_size;

    cudaFuncSetAttribute(gemm_kernel<0>, cudaFuncAttributeMaxDynamicSharedMemorySize, SMEM_BYTES);
    cudaFuncSetAttribute(gemm_kernel<1>, cudaFuncAttributeMaxDynamicSharedMemorySize, SMEM_BYTES);

    pack_a1 <<<(BSZ * 512  + 255) / 256, 256>>>(q1, x);
    pack_a2q<<<(BSZ * 512  + 255) / 256, 256>>>(q2);
    pack_w1 <<<(NMID * KD1 / 2 + 255) / 256, 256>>>(w1);
    pack_wcat<<<(NOUT * KD2 + 255) / 256, 256>>>(w2, wsk);

    dim3 g1(NMID / BN, BSZ / BM);   // (8, 128)
    gemm_kernel<0><<<g1, 256, SMEM_BYTES>>>(b1, nullptr, s1, bi1, mu1, va1, nullptr);

    dim3 g2(NOUT / BN, BSZ / BM);   // (4, 128)
    gemm_kernel<1><<<g2, 256, SMEM_BYTES>>>(b2, bsk, s2, bi2, mu2, va2, out);
}